// round 8
// baseline (speedup 1.0000x reference)
#include <cuda_runtime.h>

#define TT   1024
#define BB   512
#define IND  64
#define HIDD 256
#define OUTD 32
#define TS   32    // timestep tile

typedef unsigned long long u64;

// Rounding contract (verified bitwise vs reference, rel_err 7.6e-8):
//  - dot products: single accumulator, ascending-k __fmaf_rn chain
//  - bias added after, separate __fadd_rn
//  - LIF: mem = __fmaf_rn(0.92, mem, cur) - reset (reset detached, prev mem)
//  - spike: (mem - 1.0f) > 0
// Bitwise-neutral exploits: fma.rn.f32x2 packs independent (t, t+1) chains;
// layer 2 = sparse ascending-k __fadd_rn sum over ballot-mask set bits.
// Structure: warps 0-3 = layer-1 producers (each thread owns h and h+128),
// warps 4-7 = layer-2 consumers one tile behind (double-buffered masks).

__device__ __forceinline__ u64 ffma2(u64 a, u64 b, u64 c) {
    u64 d;
    asm("fma.rn.f32x2 %0, %1, %2, %3;" : "=l"(d) : "l"(a), "l"(b), "l"(c));
    return d;
}
__device__ __forceinline__ u64 dup2(float w) {   // (w, w) packed
    u64 d;
    asm("mov.b64 %0, {%1, %1};" : "=l"(d) : "f"(w));
    return d;
}
__device__ __forceinline__ float lo2(u64 v) { return ((float2*)&v)->x; }
__device__ __forceinline__ float hi2(u64 v) { return ((float2*)&v)->y; }

__global__ void __launch_bounds__(256, 1) snn_kernel(
    const float* __restrict__ x,    // [T, B, IN]
    const float* __restrict__ W1,   // [HID, IN]
    const float* __restrict__ b1,   // [HID]
    const float* __restrict__ W2,   // [OUT, HID]
    const float* __restrict__ b2,   // [OUT]
    float* __restrict__ out)        // [2, T, B, OUT] (spk2 then mem2)
{
    __shared__ __align__(16) float2   xq[TS / 2][IND];   // (t,t+1) pairs, 8 KB
    __shared__ __align__(16) unsigned msk[2][TS][8];     // double-buffered masks
    __shared__ __align__(16) float    w2s[HIDD][OUTD];   // W2 transposed, 32 KB
    __shared__ __align__(16) float    red[TS][OUTD];     // cur2 staging, 4 KB

    const int b   = blockIdx.x;
    const int tid = threadIdx.x;
    const int o   = tid & 31;

    // stage W2 transposed: w2s[k][o]  (all threads)
    for (int e = tid; e < OUTD * HIDD; e += 256) {
        w2s[e % HIDD][e / HIDD] = W2[e];
    }

    // ---- producer state (threads 0..127): h = tid and h+128 ----
    u64   w1ad[IND];   // weights for h, pre-duplicated for f32x2
    float w1bs[IND];   // weights for h+128, scalar (dup'd in-loop)
    float b1a = 0.0f, b1b = 0.0f, mem1a = 0.0f, mem1b = 0.0f;
    if (tid < 128) {
        #pragma unroll
        for (int k = 0; k < IND; k++) w1ad[k] = dup2(W1[tid * IND + k]);
        #pragma unroll
        for (int k = 0; k < IND; k++) w1bs[k] = W1[(tid + 128) * IND + k];
        b1a = b1[tid];
        b1b = b1[tid + 128];
    }

    // ---- consumer state (threads 128..255) ----
    float b2o = 0.0f, mem2 = 0.0f;
    const int cw = (tid >> 5) - 4;   // consumer warp 0..3
    if (tid >= 128) b2o = b2[o];

    __syncthreads();

    for (int tile = 0; tile <= TT / TS; tile++) {
        // ================= producers: current tile =================
        if (tile < TT / TS && tid < 128) {
            const int t0 = tile * TS;
            // stage x tile as (t, t+1) interleaved pairs (256 tasks / 128 thr)
            #pragma unroll
            for (int i = 0; i < 2; i++) {
                int e  = tid + 128 * i;
                int tp = e >> 4, c = e & 15;
                float4 a = ((const float4*)(x + ((size_t)(t0 + 2 * tp)     * BB + b) * IND))[c];
                float4 d = ((const float4*)(x + ((size_t)(t0 + 2 * tp + 1) * BB + b) * IND))[c];
                float4* q = (float4*)&xq[tp][c * 4];
                q[0] = make_float4(a.x, d.x, a.y, d.y);
                q[1] = make_float4(a.z, d.z, a.w, d.w);
            }
            asm volatile("bar.sync 1, 128;" ::: "memory");  // producers only

            const int wid = tid >> 5;
            for (int g = 0; g < 8; g++) {        // t = 4g .. 4g+3
                const ulonglong2* r0 = (const ulonglong2*)xq[2 * g];
                const ulonglong2* r1 = (const ulonglong2*)xq[2 * g + 1];
                u64 aa0 = 0ull, aa1 = 0ull;      // h chains (t-pairs)
                u64 ab0 = 0ull, ab1 = 0ull;      // h+128 chains
                #pragma unroll
                for (int kc = 0; kc < IND / 2; kc++) {
                    ulonglong2 v = r0[kc];       // k=2kc,2kc+1 for t=4g,4g+1
                    ulonglong2 u = r1[kc];       // same, t=4g+2,4g+3
                    u64 wa = w1ad[2 * kc];
                    u64 wb = w1ad[2 * kc + 1];
                    u64 wc = dup2(w1bs[2 * kc]);
                    u64 wd = dup2(w1bs[2 * kc + 1]);
                    aa0 = ffma2(v.x, wa, aa0);  aa0 = ffma2(v.y, wb, aa0);
                    aa1 = ffma2(u.x, wa, aa1);  aa1 = ffma2(u.y, wb, aa1);
                    ab0 = ffma2(v.x, wc, ab0);  ab0 = ffma2(v.y, wd, ab0);
                    ab1 = ffma2(u.x, wc, ab1);  ab1 = ffma2(u.y, wd, ab1);
                }
                float ca[4] = {lo2(aa0), hi2(aa0), lo2(aa1), hi2(aa1)};
                float cb[4] = {lo2(ab0), hi2(ab0), lo2(ab1), hi2(ab1)};
                #pragma unroll
                for (int i = 0; i < 4; i++) {    // LIF ascending t, both h
                    int t = 4 * g + i;
                    float cur = __fadd_rn(ca[i], b1a);
                    float r   = (mem1a > 1.0f) ? 1.0f : 0.0f;
                    mem1a = __fsub_rn(__fmaf_rn(0.92f, mem1a, cur), r);
                    unsigned bal = __ballot_sync(0xffffffffu,
                                        __fsub_rn(mem1a, 1.0f) > 0.0f);
                    cur = __fadd_rn(cb[i], b1b);
                    r   = (mem1b > 1.0f) ? 1.0f : 0.0f;
                    mem1b = __fsub_rn(__fmaf_rn(0.92f, mem1b, cur), r);
                    unsigned bal2 = __ballot_sync(0xffffffffu,
                                        __fsub_rn(mem1b, 1.0f) > 0.0f);
                    if ((tid & 31) == 0) {
                        msk[tile & 1][t][wid]     = bal;   // h window
                        msk[tile & 1][t][wid + 4] = bal2;  // h+128 window
                    }
                }
            }
        }

        // ================= consumers: previous tile =================
        if (tile > 0 && tid >= 128) {
            const int pb  = (tile - 1) & 1;
            const int t0p = (tile - 1) * TS;
            #pragma unroll
            for (int j = 0; j < 8; j++) {
                int t = cw + 4 * j;
                float acc = 0.0f;
                #pragma unroll
                for (int w = 0; w < 8; w++) {
                    unsigned m = msk[pb][t][w];          // warp-uniform
                    while (m) {
                        int k = __ffs(m) - 1;
                        acc = __fadd_rn(acc, w2s[w * 32 + k][o]);
                        m &= m - 1;
                    }
                }
                red[t][o] = __fadd_rn(acc, b2o);
            }
            asm volatile("bar.sync 2, 128;" ::: "memory");  // consumers only
            if (cw == 0) {   // warp 4: mem2 recurrence + store
                #pragma unroll 4
                for (int t = 0; t < TS; t++) {
                    float cur2 = red[t][o];
                    float r2 = (mem2 > 1.0f) ? 1.0f : 0.0f;
                    mem2 = __fsub_rn(__fmaf_rn(0.92f, mem2, cur2), r2);
                    float s2 = (__fsub_rn(mem2, 1.0f) > 0.0f) ? 1.0f : 0.0f;
                    size_t idx = ((size_t)(t0p + t) * BB + b) * OUTD + o;
                    out[idx] = s2;                              // spk2_rec
                    out[(size_t)TT * BB * OUTD + idx] = mem2;   // mem2_rec
                }
            }
        }

        __syncthreads();   // tile boundary: flips mask buffers
    }
}

extern "C" void kernel_launch(void* const* d_in, const int* in_sizes, int n_in,
                              void* d_out, int out_size) {
    const float* x  = (const float*)d_in[0];  // spike_input [1024,512,64]
    const float* W1 = (const float*)d_in[1];  // [256,64]
    const float* b1 = (const float*)d_in[2];  // [256]
    const float* W2 = (const float*)d_in[3];  // [32,256]
    const float* b2 = (const float*)d_in[4];  // [32]
    float* out = (float*)d_out;               // 2*1024*512*32 floats

    snn_kernel<<<BB, 256>>>(x, W1, b1, W2, b2, out);
}

// round 9
// speedup vs baseline: 1.5102x; 1.5102x over previous
#include <cuda_runtime.h>

#define TT   1024
#define BB   512
#define IND  64
#define HIDD 256
#define OUTD 32
#define TS   32
#define NT   (TT / TS)

typedef unsigned long long u64;

// Rounding contract (verified bitwise vs reference, rel_err 7.6e-8):
//  - dot products: single accumulator, ascending-k __fmaf_rn chain
//  - bias added after, separate __fadd_rn
//  - LIF: mem = __fmaf_rn(0.92, mem, cur) - reset (reset detached, prev mem)
//  - spike: (mem - 1.0f) > 0
// Bitwise-neutral exploits: fma.rn.f32x2 packs independent (t,t+1) chains;
// layer 2 = sparse ascending-k __fadd_rn sum over ballot-mask set bits,
// 4 independent chains round-robined for ILP (adding a selected 0.0f is
// value-neutral). mem2 for tile i-1 overlaps layer-2 of tile i (warp 0).

__device__ __forceinline__ u64 ffma2(u64 a, u64 b, u64 c) {
    u64 d;
    asm("fma.rn.f32x2 %0, %1, %2, %3;" : "=l"(d) : "l"(a), "l"(b), "l"(c));
    return d;
}
__device__ __forceinline__ u64 dup2(float w) {
    u64 d;
    asm("mov.b64 %0, {%1, %1};" : "=l"(d) : "f"(w));
    return d;
}
__device__ __forceinline__ float lo2(u64 v) { return ((float2*)&v)->x; }
__device__ __forceinline__ float hi2(u64 v) { return ((float2*)&v)->y; }

// one round-robin step of a sparse chain: add selected weight or 0.0f
#define SPARSE_STEP(m, a, wp)                              \
    {                                                      \
        int ko = __ffs(m);                                 \
        int kk = (ko > 0) ? ko - 1 : 0;                    \
        float v = wp[kk * OUTD];                           \
        a = __fadd_rn(a, (ko > 0) ? v : 0.0f);             \
        m &= m - 1;                                        \
    }

__global__ void __launch_bounds__(256, 2) snn_kernel(
    const float* __restrict__ x,    // [T, B, IN]
    const float* __restrict__ W1,   // [HID, IN]
    const float* __restrict__ b1,   // [HID]
    const float* __restrict__ W2,   // [OUT, HID]
    const float* __restrict__ b2,   // [OUT]
    float* __restrict__ out)        // [2, T, B, OUT] (spk2 then mem2)
{
    __shared__ __align__(16) float2   xq[TS / 2][IND];    // (t,t+1) pairs, 8 KB
    __shared__ __align__(16) unsigned msk[2][TS][8];      // dbuf masks, 2 KB
    __shared__ __align__(16) float    w2s[HIDD][OUTD];    // W2^T, 32 KB
    __shared__ __align__(16) float    red[2][TS][OUTD];   // dbuf cur2, 8 KB

    const int b   = blockIdx.x;
    const int tid = threadIdx.x;   // layer 1: thread = hidden unit
    const int o   = tid & 31;
    const int tg  = tid >> 5;      // warp id; layer 2 t-group
    const int stp = tid >> 4;      // staging t-pair 0..15
    const int skc = tid & 15;      // staging chunk 0..15

    for (int e = tid; e < OUTD * HIDD; e += 256) {
        w2s[e % HIDD][e / HIDD] = W2[e];
    }

    float w1r[IND];
    #pragma unroll
    for (int k = 0; k < IND; k++) w1r[k] = W1[tid * IND + k];

    const float b1h = b1[tid];
    const float b2o = b2[o];
    float mem1 = 0.0f, mem2 = 0.0f;

    for (int tile = 0; tile <= NT; tile++) {
        const int cb = tile & 1;

        // ---- a) stage x tile as (t,t+1) interleaved pairs ----
        if (tile < NT) {
            const int t0 = tile * TS;
            float4 a = ((const float4*)(x + ((size_t)(t0 + 2 * stp)     * BB + b) * IND))[skc];
            float4 d = ((const float4*)(x + ((size_t)(t0 + 2 * stp + 1) * BB + b) * IND))[skc];
            float4* q = (float4*)&xq[stp][skc * 4];
            q[0] = make_float4(a.x, d.x, a.y, d.y);
            q[1] = make_float4(a.z, d.z, a.w, d.w);
        }
        __syncthreads();   // S_A: xq staged; red(tile-1) visible

        // ---- c) layer 1 + mem1 recurrence + ballots -> msk[cb] ----
        if (tile < NT) {
            for (int g = 0; g < 8; g++) {           // t = 4g .. 4g+3
                const ulonglong2* r0 = (const ulonglong2*)xq[2 * g];
                const ulonglong2* r1 = (const ulonglong2*)xq[2 * g + 1];
                u64 acc0 = 0ull, acc1 = 0ull;
                #pragma unroll
                for (int kc = 0; kc < IND / 2; kc++) {
                    ulonglong2 v0 = r0[kc];
                    ulonglong2 v1 = r1[kc];
                    u64 wa = dup2(w1r[2 * kc]);
                    u64 wb = dup2(w1r[2 * kc + 1]);
                    acc0 = ffma2(v0.x, wa, acc0);
                    acc0 = ffma2(v0.y, wb, acc0);
                    acc1 = ffma2(v1.x, wa, acc1);
                    acc1 = ffma2(v1.y, wb, acc1);
                }
                float c4[4] = {lo2(acc0), hi2(acc0), lo2(acc1), hi2(acc1)};
                #pragma unroll
                for (int i = 0; i < 4; i++) {       // LIF ascending t
                    float cur1 = __fadd_rn(c4[i], b1h);
                    float r1f  = (mem1 > 1.0f) ? 1.0f : 0.0f;
                    mem1 = __fsub_rn(__fmaf_rn(0.92f, mem1, cur1), r1f);
                    unsigned bal = __ballot_sync(0xffffffffu,
                                       __fsub_rn(mem1, 1.0f) > 0.0f);
                    if (o == 0) msk[cb][4 * g + i][tg] = bal;
                }
            }
        }
        __syncthreads();   // S_B: msk[cb] ready

        // ---- e1) warp 0: mem2 recurrence + store for tile-1 ----
        if (tile > 0 && tg == 0) {
            const int pb  = (tile - 1) & 1;
            const int t0p = (tile - 1) * TS;
            #pragma unroll 4
            for (int t = 0; t < TS; t++) {
                float cur2 = red[pb][t][o];
                float r2 = (mem2 > 1.0f) ? 1.0f : 0.0f;
                mem2 = __fsub_rn(__fmaf_rn(0.92f, mem2, cur2), r2);
                float s2 = (__fsub_rn(mem2, 1.0f) > 0.0f) ? 1.0f : 0.0f;
                size_t idx = ((size_t)(t0p + t) * BB + b) * OUTD + o;
                out[idx] = s2;                              // spk2_rec
                out[(size_t)TT * BB * OUTD + idx] = mem2;   // mem2_rec
            }
        }

        // ---- e2) layer 2: 4 round-robined sparse chains -> red[cb] ----
        if (tile < NT) {
            float a0 = 0.0f, a1 = 0.0f, a2 = 0.0f, a3 = 0.0f;
            #pragma unroll
            for (int w = 0; w < 8; w++) {
                unsigned m0 = msk[cb][tg][w];        // warp-uniform
                unsigned m1 = msk[cb][tg + 8][w];
                unsigned m2 = msk[cb][tg + 16][w];
                unsigned m3 = msk[cb][tg + 24][w];
                const float* wp = &w2s[w * 32][o];
                while (m0 | m1 | m2 | m3) {          // uniform branch
                    SPARSE_STEP(m0, a0, wp)
                    SPARSE_STEP(m1, a1, wp)
                    SPARSE_STEP(m2, a2, wp)
                    SPARSE_STEP(m3, a3, wp)
                }
            }
            red[cb][tg][o]      = __fadd_rn(a0, b2o);
            red[cb][tg + 8][o]  = __fadd_rn(a1, b2o);
            red[cb][tg + 16][o] = __fadd_rn(a2, b2o);
            red[cb][tg + 24][o] = __fadd_rn(a3, b2o);
        }
        // no barrier here: next S_A orders red/msk handoff
    }
}

extern "C" void kernel_launch(void* const* d_in, const int* in_sizes, int n_in,
                              void* d_out, int out_size) {
    const float* x  = (const float*)d_in[0];  // spike_input [1024,512,64]
    const float* W1 = (const float*)d_in[1];  // [256,64]
    const float* b1 = (const float*)d_in[2];  // [256]
    const float* W2 = (const float*)d_in[3];  // [32,256]
    const float* b2 = (const float*)d_in[4];  // [32]
    float* out = (float*)d_out;               // 2*1024*512*32 floats

    snn_kernel<<<BB, 256>>>(x, W1, b1, W2, b2, out);
}